// round 6
// baseline (speedup 1.0000x reference)
#include <cuda_runtime.h>
#include <cstddef>

#define NB    16
#define HH    512
#define WWID  512
#define NPB   20000
#define NPTS  (NB * NPB)          // 320000
#define EPSV  1e-5f
#define NBLK  1250                // NPTS / 256 exactly

// ---------------- scratch ----------------
__device__ int g_map[NB * HH * WWID];
__device__ int g_nbr[9 * NPTS];                    // packed (j<<4 | tap), slot-major
__device__ int g_cntv[NPTS];
__device__ __align__(16) float g_y1[NPTS * 8];
__device__ __align__(16) float g_y2[NPTS * 16];
__device__ __align__(16) float g_y3[NPTS * 32];
__device__ float g_p1[NBLK * 16];                  // conv1 partials (8 sum | 8 sq)
__device__ float g_p2[NBLK * 32];                  // conv2 partials
__device__ float g_p3[NBLK * 64];                  // conv3 partials (both halves)
__device__ float g_bn1[16], g_bn2[32], g_bn3[64];  // folded scale | shift
__device__ unsigned g_pool[NB * 32];
__device__ unsigned g_ctr[3];

// ---------------- helpers ----------------
// block stats: each thread holds acc[NCH]; deterministic warp+block reduce, write row.
template <int NCH>
__device__ __forceinline__ void block_stats(const float* acc, float* row,
                                            int sum_off, int sq_off) {
    __shared__ float s_red[8 * 2 * NCH];
    int lane = threadIdx.x & 31, warp = threadIdx.x >> 5;
#pragma unroll
    for (int co = 0; co < NCH; co++) {
        float s = acc[co], q = acc[co] * acc[co];
#pragma unroll
        for (int off = 16; off; off >>= 1) {
            s += __shfl_down_sync(0xffffffffu, s, off);
            q += __shfl_down_sync(0xffffffffu, q, off);
        }
        if (lane == 0) { s_red[warp * 2 * NCH + co] = s; s_red[warp * 2 * NCH + NCH + co] = q; }
    }
    __syncthreads();
    if (threadIdx.x < 2 * NCH) {
        float t = 0.f;
#pragma unroll
        for (int w = 0; w < 8; w++) t += s_red[w * 2 * NCH + threadIdx.x];
        int off = (threadIdx.x < NCH) ? (sum_off + threadIdx.x) : (sq_off + threadIdx.x - NCH);
        __stcg(&row[off], t);
    }
}

// last-block fold: sum nrows rows of width 2*C, compute BN scale/shift into bn[2*C].
template <int C>
__device__ __forceinline__ void fold_bn(const float* part, int nrows,
                                        const float* gamma, const float* beta, float* bn) {
    __shared__ float s4[4][64];
    int c = threadIdx.x & 63, seg = threadIdx.x >> 6;
    float a = 0.f;
    if (c < 2 * C)
        for (int r = seg; r < nrows; r += 4) a += __ldcg(&part[r * 2 * C + c]);
    s4[seg][c] = a;
    __syncthreads();
    if ((int)threadIdx.x < C) {
        int c0 = threadIdx.x;
        float S = s4[0][c0] + s4[1][c0] + s4[2][c0] + s4[3][c0];
        float Q = s4[0][C + c0] + s4[1][C + c0] + s4[2][C + c0] + s4[3][C + c0];
        float m = S / (float)NPTS;
        float var = Q / (float)NPTS - m * m;
        float sc = gamma[c0] * rsqrtf(var + EPSV);
        bn[c0] = sc;
        bn[C + c0] = beta[c0] - m * sc;
    }
}

#define LAST_BLOCK_GATE(ctr, target, lastvar)                        \
    __threadfence();                                                 \
    __syncthreads();                                                 \
    if (threadIdx.x == 0)                                            \
        lastvar = (atomicAdd(&(ctr), 1u) == (unsigned)(target) - 1u);\
    __syncthreads();

// ---------------- 1: clear map ----------------
__global__ void k_clear_map() {
    int i = blockIdx.x * blockDim.x + threadIdx.x;
    int stride = gridDim.x * blockDim.x;
    int4* m4 = reinterpret_cast<int4*>(g_map);
    const int n4 = NB * HH * WWID / 4;
    int4 neg = make_int4(-1, -1, -1, -1);
    for (int t = i; t < n4; t += stride) m4[t] = neg;
}

// ---------------- 2: clear pool + counters ----------------
__global__ void k_clear_misc() {
    int i = threadIdx.x;
    if (i < NB * 32) g_pool[i] = 0u;
    if (i < 3) g_ctr[i] = 0u;
}

// ---------------- 3: scatter ----------------
__global__ void k_scatter(const int* __restrict__ idx) {
    int i = blockIdx.x * blockDim.x + threadIdx.x;
    if (i < NPTS) {
        int b = idx[3 * i], y = idx[3 * i + 1], x = idx[3 * i + 2];
        g_map[(b << 18) | (y << 9) | x] = i;
    }
}

// ---------------- 4: conv1 + list build + stats + BN1 fold ----------------
__global__ __launch_bounds__(256)
void k_build(const int* __restrict__ idx, const float* __restrict__ feats,
             const float* __restrict__ w1,
             const float* __restrict__ g1, const float* __restrict__ b1)
{
    __shared__ float ws[72];
    __shared__ bool s_last;
    if (threadIdx.x < 72) ws[threadIdx.x] = w1[threadIdx.x];
    __syncthreads();

    int i = blockIdx.x * 256 + threadIdx.x;
    int b = idx[3 * i], y = idx[3 * i + 1], x = idx[3 * i + 2];
    int base = b << 18;

    int jj[9];
#pragma unroll
    for (int t = 0; t < 9; t++) {
        int ny = y + t / 3 - 1, nx = x + t % 3 - 1;
        bool ok = ((unsigned)ny < (unsigned)HH) && ((unsigned)nx < (unsigned)WWID);
        int nyc = ok ? ny : y, nxc = ok ? nx : x;
        int j = g_map[base + (nyc << 9) + nxc];
        jj[t] = ok ? j : -1;
    }

    float acc[8];
#pragma unroll
    for (int c = 0; c < 8; c++) acc[c] = 0.f;
    int cnt = 0;
#pragma unroll
    for (int t = 0; t < 9; t++) {
        if (jj[t] >= 0) {
            g_nbr[cnt * NPTS + i] = (jj[t] << 4) | t;
            cnt++;
            float v = feats[jj[t]];
#pragma unroll
            for (int co = 0; co < 8; co++)
                acc[co] = fmaf(v, ws[t * 8 + co], acc[co]);
        }
    }
    g_cntv[i] = cnt;

    float4* orow = reinterpret_cast<float4*>(g_y1 + (size_t)i * 8);
    orow[0] = make_float4(acc[0], acc[1], acc[2], acc[3]);
    orow[1] = make_float4(acc[4], acc[5], acc[6], acc[7]);

    block_stats<8>(acc, &g_p1[blockIdx.x * 16], 0, 8);
    LAST_BLOCK_GATE(g_ctr[0], NBLK, s_last);
    if (s_last) fold_bn<8>(g_p1, NBLK, g1, b1, g_bn1);
}

// ---------------- 5: conv2 (CIN=8 -> COUT=16) + stats + BN2 fold ----------------
__global__ __launch_bounds__(256, 4)
void k_conv2(const float* __restrict__ w2,
             const float* __restrict__ g2, const float* __restrict__ b2)
{
    __shared__ float s_ws[9 * 8 * 16];
    __shared__ float s_ab[16];
    __shared__ bool s_last;
    for (int t = threadIdx.x; t < 9 * 8 * 16; t += 256) s_ws[t] = w2[t];
    if (threadIdx.x < 16) s_ab[threadIdx.x] = g_bn1[threadIdx.x];
    __syncthreads();

    int i = blockIdx.x * 256 + threadIdx.x;
    int cnt = g_cntv[i];
    int pcur = g_nbr[i];
    float acc[16];
#pragma unroll
    for (int c = 0; c < 16; c++) acc[c] = 0.f;

    for (int s = 0; s < cnt; s++) {
        int pnext = (s + 1 < cnt) ? g_nbr[(s + 1) * NPTS + i] : 0;   // prefetch
        int j = pcur >> 4, tp = pcur & 15;
        const float4* inr = reinterpret_cast<const float4*>(g_y1 + (size_t)j * 8);
        float4 r0 = inr[0], r1 = inr[1];
        const float* wr = s_ws + tp * 128;
        float vv[8] = {r0.x, r0.y, r0.z, r0.w, r1.x, r1.y, r1.z, r1.w};
#pragma unroll
        for (int ci = 0; ci < 8; ci++) {
            float v = fmaxf(fmaf(vv[ci], s_ab[ci], s_ab[8 + ci]), 0.f);
#pragma unroll
            for (int co = 0; co < 16; co++)
                acc[co] = fmaf(v, wr[ci * 16 + co], acc[co]);
        }
        pcur = pnext;
    }

    float4* orow = reinterpret_cast<float4*>(g_y2 + (size_t)i * 16);
#pragma unroll
    for (int c4 = 0; c4 < 4; c4++)
        orow[c4] = make_float4(acc[4 * c4], acc[4 * c4 + 1], acc[4 * c4 + 2], acc[4 * c4 + 3]);

    block_stats<16>(acc, &g_p2[blockIdx.x * 32], 0, 16);
    LAST_BLOCK_GATE(g_ctr[1], NBLK, s_last);
    if (s_last) fold_bn<16>(g_p2, NBLK, g2, b2, g_bn2);
}

// ---------------- 6: conv3 (CIN=16 -> COUT=32, channel-half split) ----------------
__global__ __launch_bounds__(256, 4)
void k_conv3(const float* __restrict__ w3,
             const float* __restrict__ g3, const float* __restrict__ b3)
{
    __shared__ float s_ws[9 * 16 * 16];
    __shared__ float s_ab[32];
    __shared__ bool s_last;
    int half = blockIdx.y;                     // 0 or 1: output channels [half*16, +16)
    for (int t = threadIdx.x; t < 9 * 16 * 16; t += 256) {
        int tap = t >> 8, rem = t & 255;
        int ci = rem >> 4, co = rem & 15;
        s_ws[t] = w3[(tap * 16 + ci) * 32 + half * 16 + co];
    }
    if (threadIdx.x < 32) s_ab[threadIdx.x] = g_bn2[threadIdx.x];
    __syncthreads();

    int i = blockIdx.x * 256 + threadIdx.x;
    int cnt = g_cntv[i];
    int pcur = g_nbr[i];
    float acc[16];
#pragma unroll
    for (int c = 0; c < 16; c++) acc[c] = 0.f;

    for (int s = 0; s < cnt; s++) {
        int pnext = (s + 1 < cnt) ? g_nbr[(s + 1) * NPTS + i] : 0;   // prefetch
        int j = pcur >> 4, tp = pcur & 15;
        const float4* inr = reinterpret_cast<const float4*>(g_y2 + (size_t)j * 16);
        float4 r0 = inr[0], r1 = inr[1], r2 = inr[2], r3 = inr[3];
        const float* wr = s_ws + tp * 256;
        float vv[16] = {r0.x, r0.y, r0.z, r0.w, r1.x, r1.y, r1.z, r1.w,
                        r2.x, r2.y, r2.z, r2.w, r3.x, r3.y, r3.z, r3.w};
#pragma unroll
        for (int ci = 0; ci < 16; ci++) {
            float v = fmaxf(fmaf(vv[ci], s_ab[ci], s_ab[16 + ci]), 0.f);
#pragma unroll
            for (int co = 0; co < 16; co++)
                acc[co] = fmaf(v, wr[ci * 16 + co], acc[co]);
        }
        pcur = pnext;
    }

    float4* orow = reinterpret_cast<float4*>(g_y3 + (size_t)i * 32 + half * 16);
#pragma unroll
    for (int c4 = 0; c4 < 4; c4++)
        orow[c4] = make_float4(acc[4 * c4], acc[4 * c4 + 1], acc[4 * c4 + 2], acc[4 * c4 + 3]);

    block_stats<16>(acc, &g_p3[blockIdx.x * 64], half * 16, 32 + half * 16);
    LAST_BLOCK_GATE(g_ctr[2], 2 * NBLK, s_last);
    if (s_last) fold_bn<32>(g_p3, NBLK, g3, b3, g_bn3);
}

// ---------------- 7: BN3+ReLU fused segment-max pool ----------------
__global__ void k_pool(const int* __restrict__ idx) {
    int bb = blockIdx.y;
    int l = blockIdx.x * 256 + threadIdx.x;
    __shared__ float s_ab[64];
    if (threadIdx.x < 64) s_ab[threadIdx.x] = g_bn3[threadIdx.x];
    __syncthreads();
    float v[32];
#pragma unroll
    for (int c = 0; c < 32; c++) v[c] = 0.f;
    if (l < NPB) {
        int i = bb * NPB + l;
        const float4* r = reinterpret_cast<const float4*>(g_y3 + (size_t)i * 32);
#pragma unroll
        for (int c4 = 0; c4 < 8; c4++) {
            float4 t = r[c4];
            float tv[4] = {t.x, t.y, t.z, t.w};
#pragma unroll
            for (int u = 0; u < 4; u++) {
                int c = c4 * 4 + u;
                v[c] = fmaxf(fmaf(tv[u], s_ab[c], s_ab[32 + c]), 0.f);
            }
        }
    }
    __shared__ float red[8][32];
    int lane = threadIdx.x & 31, wid = threadIdx.x >> 5;
#pragma unroll
    for (int c = 0; c < 32; c++) {
        float m = v[c];
#pragma unroll
        for (int off = 16; off; off >>= 1)
            m = fmaxf(m, __shfl_down_sync(0xffffffffu, m, off));
        if (lane == 0) red[wid][c] = m;
    }
    __syncthreads();
    if (threadIdx.x < 32) {
        float m = 0.f;
#pragma unroll
        for (int wdx = 0; wdx < 8; wdx++) m = fmaxf(m, red[wdx][threadIdx.x]);
        atomicMax(&g_pool[bb * 32 + threadIdx.x], __float_as_uint(m));
    }
}

// ---------------- 8: FC + ReLU ----------------
__global__ void k_fc(const float* __restrict__ Wfc, const float* __restrict__ bfc,
                     float* __restrict__ out)
{
    int bb = blockIdx.x, co = threadIdx.x;
    __shared__ float p[32];
    if (threadIdx.x < 32) p[threadIdx.x] = __uint_as_float(g_pool[bb * 32 + threadIdx.x]);
    __syncthreads();
    float acc = bfc[co];
#pragma unroll
    for (int ci = 0; ci < 32; ci++)
        acc = fmaf(p[ci], Wfc[ci * 128 + co], acc);
    out[bb * 128 + co] = fmaxf(acc, 0.f);
}

// ---------------- launch ----------------
extern "C" void kernel_launch(void* const* d_in, const int* in_sizes, int n_in,
                              void* d_out, int out_size)
{
    const float* feats = (const float*)d_in[0];
    const int*   idx   = (const int*)d_in[1];
    const float* W1    = (const float*)d_in[2];
    const float* g1    = (const float*)d_in[3];
    const float* b1    = (const float*)d_in[4];
    const float* W2    = (const float*)d_in[5];
    const float* g2    = (const float*)d_in[6];
    const float* b2    = (const float*)d_in[7];
    const float* W3    = (const float*)d_in[8];
    const float* g3    = (const float*)d_in[9];
    const float* b3    = (const float*)d_in[10];
    const float* Wfc   = (const float*)d_in[11];
    const float* bfc   = (const float*)d_in[12];
    float* out = (float*)d_out;

    k_clear_map<<<2048, 256>>>();                       // launch 1
    k_clear_misc<<<1, 512>>>();                         // launch 2
    k_scatter<<<NBLK, 256>>>(idx);                      // launch 3
    k_build<<<NBLK, 256>>>(idx, feats, W1, g1, b1);     // launch 4
    k_conv2<<<NBLK, 256>>>(W2, g2, b2);                 // launch 5
    dim3 c3(NBLK, 2);
    k_conv3<<<c3, 256>>>(W3, g3, b3);                   // launch 6  <- ncu -s 5 -c 1
    dim3 pg((NPB + 255) / 256, NB);
    k_pool<<<pg, 256>>>(idx);                           // launch 7
    k_fc<<<NB, 128>>>(Wfc, bfc, out);                   // launch 8
}

// round 7
// speedup vs baseline: 1.3064x; 1.3064x over previous
#include <cuda_runtime.h>
#include <cstddef>

#define NB    16
#define HH    512
#define WWID  512
#define NPB   20000
#define NPTS  (NB * NPB)          // 320000
#define EPSV  1e-5f
#define NBLK  1250                // NPTS / 256 exactly
#define FBLKS 64
#define FCHUNK 20                 // 64*20 >= 1250

// ---------------- scratch ----------------
__device__ int g_map[NB * HH * WWID + 8];          // i+1 encoding; 0 = empty (zero-init)
__device__ int g_nbr[9 * NPTS];                    // packed (j<<4 | tap), slot-major by i
__device__ int g_cntv[NPTS];                       // tap count per point (by i)
__device__ int g_hist[NBLK * 10];                  // per-build-block cnt histogram
__device__ int g_boff[NBLK * 10];                  // per-block per-bin exclusive offsets
__device__ int g_binbase[10];                      // global bin bases
__device__ int g_perm[NPTS];                       // sorted-by-cnt point order
__device__ int g_cntp[NPTS];                       // cnt in perm order
__device__ __align__(16) float g_y1[NPTS * 8];
__device__ __align__(16) float g_y2[NPTS * 16];
__device__ __align__(16) float g_y3[NPTS * 32];
__device__ float g_part[NBLK * 64];                // stride-64 rows: [sum(C) | sumsq(C)]
__device__ float g_part2[FBLKS * 64];
__device__ float g_bn1[16], g_bn2[32], g_bn3[64];  // folded scale | shift
__device__ unsigned g_pool[NB * 32];
__device__ unsigned g_fctr[3];

// ---------------- block stats: acc[NCH] per thread -> g_part row ----------------
template <int NCH>
__device__ __forceinline__ void block_stats(const float* acc, int blk) {
    __shared__ float s_red[8 * 2 * NCH];
    int lane = threadIdx.x & 31, warp = threadIdx.x >> 5;
#pragma unroll
    for (int co = 0; co < NCH; co++) {
        float s = acc[co], q = acc[co] * acc[co];
#pragma unroll
        for (int off = 16; off; off >>= 1) {
            s += __shfl_down_sync(0xffffffffu, s, off);
            q += __shfl_down_sync(0xffffffffu, q, off);
        }
        if (lane == 0) { s_red[warp * 2 * NCH + co] = s; s_red[warp * 2 * NCH + NCH + co] = q; }
    }
    __syncthreads();
    if (threadIdx.x < 2 * NCH) {
        float t = 0.f;
#pragma unroll
        for (int w = 0; w < 8; w++) t += s_red[w * 2 * NCH + threadIdx.x];
        g_part[blk * 64 + threadIdx.x] = t;
    }
}

// ---------------- 1: scatter (i+1 encoding) + clear misc ----------------
__global__ void k_scatter(const int* __restrict__ idx) {
    int i = blockIdx.x * blockDim.x + threadIdx.x;
    if (i < NPTS) {
        int b = idx[3 * i], y = idx[3 * i + 1], x = idx[3 * i + 2];
        g_map[(b << 18) | (y << 9) | x] = i + 1;
    }
    if (i < NB * 32) g_pool[i] = 0u;
    if (i < 3) g_fctr[i] = 0u;
}

// ---------------- 2: conv1 + list build + histogram + stats ----------------
__global__ __launch_bounds__(256)
void k_build(const int* __restrict__ idx, const float* __restrict__ feats,
             const float* __restrict__ w1)
{
    __shared__ float ws[72];
    __shared__ int hist[10];
    if (threadIdx.x < 72) ws[threadIdx.x] = w1[threadIdx.x];
    if (threadIdx.x < 10) hist[threadIdx.x] = 0;
    __syncthreads();

    int i = blockIdx.x * 256 + threadIdx.x;
    int b = idx[3 * i], y = idx[3 * i + 1], x = idx[3 * i + 2];
    int base = b << 18;

    int jj[9];
#pragma unroll
    for (int t = 0; t < 9; t++) {
        int ny = y + t / 3 - 1, nx = x + t % 3 - 1;
        bool ok = ((unsigned)ny < (unsigned)HH) && ((unsigned)nx < (unsigned)WWID);
        int nyc = ok ? ny : y, nxc = ok ? nx : x;
        int j = g_map[base + (nyc << 9) + nxc];
        jj[t] = ok ? (j - 1) : -1;                 // 0 = empty -> -1
    }

    float acc[8];
#pragma unroll
    for (int c = 0; c < 8; c++) acc[c] = 0.f;
    int cnt = 0;
#pragma unroll
    for (int t = 0; t < 9; t++) {
        if (jj[t] >= 0) {
            g_nbr[cnt * NPTS + i] = (jj[t] << 4) | t;
            cnt++;
            float v = feats[jj[t]];
#pragma unroll
            for (int co = 0; co < 8; co++)
                acc[co] = fmaf(v, ws[t * 8 + co], acc[co]);
        }
    }
    g_cntv[i] = cnt;
    atomicAdd(&hist[cnt], 1);

    float4* orow = reinterpret_cast<float4*>(g_y1 + (size_t)i * 8);
    orow[0] = make_float4(acc[0], acc[1], acc[2], acc[3]);
    orow[1] = make_float4(acc[4], acc[5], acc[6], acc[7]);

    block_stats<8>(acc, blockIdx.x);
    __syncthreads();
    if (threadIdx.x < 10) g_hist[blockIdx.x * 10 + threadIdx.x] = hist[threadIdx.x];
}

// ---------------- 3: scan histograms -> per-block bin offsets + bin bases ----------
__global__ __launch_bounds__(320)
void k_scan() {
    __shared__ int s_tot[10];
    int warp = threadIdx.x >> 5, lane = threadIdx.x & 31;
    int k = warp;                                  // 10 warps, one bin each
    int running = 0;
    for (int basei = 0; basei < NBLK; basei += 32) {
        int b = basei + lane;
        int v = (b < NBLK) ? g_hist[b * 10 + k] : 0;
        int inc = v;
#pragma unroll
        for (int off = 1; off < 32; off <<= 1) {
            int n = __shfl_up_sync(0xffffffffu, inc, off);
            if (lane >= off) inc += n;
        }
        if (b < NBLK) g_boff[b * 10 + k] = running + (inc - v);
        running += __shfl_sync(0xffffffffu, inc, 31);
    }
    if (lane == 0) s_tot[k] = running;
    __syncthreads();
    if (threadIdx.x == 0) {
        int r = 0;
#pragma unroll
        for (int kk = 0; kk < 10; kk++) { g_binbase[kk] = r; r += s_tot[kk]; }
    }
}

// ---------------- 4: deterministic rank -> perm ----------------
__global__ __launch_bounds__(256)
void k_rank() {
    __shared__ int wcnt[8][10], wbase[8][10];
    int warp = threadIdx.x >> 5, lane = threadIdx.x & 31;
    if (threadIdx.x < 80) wcnt[threadIdx.x / 10][threadIdx.x % 10] = 0;
    __syncthreads();

    int i = blockIdx.x * 256 + threadIdx.x;
    int k = g_cntv[i];
    unsigned mymask = __match_any_sync(0xffffffffu, k);
    int lrank = __popc(mymask & ((1u << lane) - 1u));
    if (lane == (__ffs(mymask) - 1)) wcnt[warp][k] = __popc(mymask);
    __syncthreads();
    if (threadIdx.x < 80) {
        int w = threadIdx.x / 10, kk = threadIdx.x % 10;
        int s = 0;
        for (int w2 = 0; w2 < w; w2++) s += wcnt[w2][kk];
        wbase[w][kk] = s;
    }
    __syncthreads();
    int pos = g_binbase[k] + g_boff[blockIdx.x * 10 + k] + wbase[warp][k] + lrank;
    g_perm[pos] = i;
    g_cntp[pos] = k;
}

// ---------------- finalize: reduce g_part, fold BN ----------------
template <int C>
__global__ __launch_bounds__(256)
void k_finalize(const float* __restrict__ gamma, const float* __restrict__ beta,
                float* __restrict__ bn, int layer)
{
    int c = threadIdx.x & 63, seg = threadIdx.x >> 6;
    int g = blockIdx.x;
    __shared__ float s[4][64];
    __shared__ bool last;

    int lo = g * FCHUNK, hi = min(lo + FCHUNK, NBLK);
    float a = 0.f;
    for (int blk = lo + seg; blk < hi; blk += 4) a += g_part[blk * 64 + c];
    s[seg][c] = a;
    __syncthreads();
    if (threadIdx.x < 64)
        __stcg(&g_part2[g * 64 + threadIdx.x],
               s[0][threadIdx.x] + s[1][threadIdx.x] + s[2][threadIdx.x] + s[3][threadIdx.x]);
    __threadfence();
    __syncthreads();
    if (threadIdx.x == 0) last = (atomicAdd(&g_fctr[layer], 1u) == FBLKS - 1u);
    __syncthreads();
    if (!last) return;

    float a2 = 0.f;
#pragma unroll
    for (int kk = 0; kk < 16; kk++) a2 += __ldcg(&g_part2[(seg * 16 + kk) * 64 + c]);
    s[seg][c] = a2;
    __syncthreads();
    if (threadIdx.x < 64)
        s[0][threadIdx.x] = s[0][threadIdx.x] + s[1][threadIdx.x] + s[2][threadIdx.x] + s[3][threadIdx.x];
    __syncthreads();
    if ((int)threadIdx.x < C) {
        int c0 = threadIdx.x;
        float m = s[0][c0] / (float)NPTS;
        float var = s[0][C + c0] / (float)NPTS - m * m;
        float sc = gamma[c0] * rsqrtf(var + EPSV);
        bn[c0] = sc;
        bn[C + c0] = beta[c0] - m * sc;
    }
}

// ---------------- conv2: 8 -> 16, perm order (uniform cnt per warp) ----------------
__global__ __launch_bounds__(256, 4)
void k_conv2(const float* __restrict__ w2)
{
    __shared__ float s_ws[9 * 8 * 16];
    __shared__ float s_ab[16];
    for (int t = threadIdx.x; t < 9 * 8 * 16; t += 256) s_ws[t] = w2[t];
    if (threadIdx.x < 16) s_ab[threadIdx.x] = g_bn1[threadIdx.x];
    __syncthreads();

    int pos = blockIdx.x * 256 + threadIdx.x;
    int i = g_perm[pos];
    int cnt = g_cntp[pos];
    int pcur = g_nbr[i];
    float acc[16];
#pragma unroll
    for (int c = 0; c < 16; c++) acc[c] = 0.f;

    for (int s = 0; s < cnt; s++) {
        int pnext = (s + 1 < cnt) ? g_nbr[(s + 1) * NPTS + i] : 0;
        int j = pcur >> 4, tp = pcur & 15;
        const float4* inr = reinterpret_cast<const float4*>(g_y1 + (size_t)j * 8);
        float4 r0 = inr[0], r1 = inr[1];
        const float* wr = s_ws + tp * 128;
        float vv[8] = {r0.x, r0.y, r0.z, r0.w, r1.x, r1.y, r1.z, r1.w};
#pragma unroll
        for (int ci = 0; ci < 8; ci++) {
            float v = fmaxf(fmaf(vv[ci], s_ab[ci], s_ab[8 + ci]), 0.f);
#pragma unroll
            for (int co = 0; co < 16; co++)
                acc[co] = fmaf(v, wr[ci * 16 + co], acc[co]);
        }
        pcur = pnext;
    }

    float4* orow = reinterpret_cast<float4*>(g_y2 + (size_t)i * 16);
#pragma unroll
    for (int c4 = 0; c4 < 4; c4++)
        orow[c4] = make_float4(acc[4 * c4], acc[4 * c4 + 1], acc[4 * c4 + 2], acc[4 * c4 + 3]);

    block_stats<16>(acc, blockIdx.x);
}

// ---------------- conv3: 16 -> 32, perm order ----------------
__global__ __launch_bounds__(256, 3)
void k_conv3(const float* __restrict__ w3)
{
    __shared__ float s_ws[9 * 16 * 32];
    __shared__ float s_ab[32];
    for (int t = threadIdx.x; t < 9 * 16 * 32; t += 256) s_ws[t] = w3[t];
    if (threadIdx.x < 32) s_ab[threadIdx.x] = g_bn2[threadIdx.x];
    __syncthreads();

    int pos = blockIdx.x * 256 + threadIdx.x;
    int i = g_perm[pos];
    int cnt = g_cntp[pos];
    int pcur = g_nbr[i];
    float acc[32];
#pragma unroll
    for (int c = 0; c < 32; c++) acc[c] = 0.f;

    for (int s = 0; s < cnt; s++) {
        int pnext = (s + 1 < cnt) ? g_nbr[(s + 1) * NPTS + i] : 0;
        int j = pcur >> 4, tp = pcur & 15;
        const float4* inr = reinterpret_cast<const float4*>(g_y2 + (size_t)j * 16);
        float4 r0 = inr[0], r1 = inr[1], r2 = inr[2], r3 = inr[3];
        const float* wr = s_ws + tp * 512;
        float vv[16] = {r0.x, r0.y, r0.z, r0.w, r1.x, r1.y, r1.z, r1.w,
                        r2.x, r2.y, r2.z, r2.w, r3.x, r3.y, r3.z, r3.w};
#pragma unroll
        for (int ci = 0; ci < 16; ci++) {
            float v = fmaxf(fmaf(vv[ci], s_ab[ci], s_ab[16 + ci]), 0.f);
#pragma unroll
            for (int co = 0; co < 32; co++)
                acc[co] = fmaf(v, wr[ci * 32 + co], acc[co]);
        }
        pcur = pnext;
    }

    float4* orow = reinterpret_cast<float4*>(g_y3 + (size_t)i * 32);
#pragma unroll
    for (int c4 = 0; c4 < 8; c4++)
        orow[c4] = make_float4(acc[4 * c4], acc[4 * c4 + 1], acc[4 * c4 + 2], acc[4 * c4 + 3]);

    block_stats<32>(acc, blockIdx.x);
}

// ---------------- pool ----------------
__global__ void k_pool(const int* __restrict__ idx) {
    int bb = blockIdx.y;
    int l = blockIdx.x * 256 + threadIdx.x;
    __shared__ float s_ab[64];
    if (threadIdx.x < 64) s_ab[threadIdx.x] = g_bn3[threadIdx.x];
    __syncthreads();
    float v[32];
#pragma unroll
    for (int c = 0; c < 32; c++) v[c] = 0.f;
    if (l < NPB) {
        int i = bb * NPB + l;
        const float4* r = reinterpret_cast<const float4*>(g_y3 + (size_t)i * 32);
#pragma unroll
        for (int c4 = 0; c4 < 8; c4++) {
            float4 t = r[c4];
            float tv[4] = {t.x, t.y, t.z, t.w};
#pragma unroll
            for (int u = 0; u < 4; u++) {
                int c = c4 * 4 + u;
                v[c] = fmaxf(fmaf(tv[u], s_ab[c], s_ab[32 + c]), 0.f);
            }
        }
    }
    __shared__ float red[8][32];
    int lane = threadIdx.x & 31, wid = threadIdx.x >> 5;
#pragma unroll
    for (int c = 0; c < 32; c++) {
        float m = v[c];
#pragma unroll
        for (int off = 16; off; off >>= 1)
            m = fmaxf(m, __shfl_down_sync(0xffffffffu, m, off));
        if (lane == 0) red[wid][c] = m;
    }
    __syncthreads();
    if (threadIdx.x < 32) {
        float m = 0.f;
#pragma unroll
        for (int wdx = 0; wdx < 8; wdx++) m = fmaxf(m, red[wdx][threadIdx.x]);
        atomicMax(&g_pool[bb * 32 + threadIdx.x], __float_as_uint(m));
    }
}

// ---------------- FC ----------------
__global__ void k_fc(const float* __restrict__ Wfc, const float* __restrict__ bfc,
                     float* __restrict__ out)
{
    int bb = blockIdx.x, co = threadIdx.x;
    __shared__ float p[32];
    if (threadIdx.x < 32) p[threadIdx.x] = __uint_as_float(g_pool[bb * 32 + threadIdx.x]);
    __syncthreads();
    float acc = bfc[co];
#pragma unroll
    for (int ci = 0; ci < 32; ci++)
        acc = fmaf(p[ci], Wfc[ci * 128 + co], acc);
    out[bb * 128 + co] = fmaxf(acc, 0.f);
}

// ---------------- unscatter: restore map to empty (0) for next replay ----------------
__global__ void k_unscatter(const int* __restrict__ idx) {
    int i = blockIdx.x * blockDim.x + threadIdx.x;
    if (i < NPTS) {
        int b = idx[3 * i], y = idx[3 * i + 1], x = idx[3 * i + 2];
        g_map[(b << 18) | (y << 9) | x] = 0;
    }
}

// ---------------- launch ----------------
extern "C" void kernel_launch(void* const* d_in, const int* in_sizes, int n_in,
                              void* d_out, int out_size)
{
    const float* feats = (const float*)d_in[0];
    const int*   idx   = (const int*)d_in[1];
    const float* W1    = (const float*)d_in[2];
    const float* g1    = (const float*)d_in[3];
    const float* b1    = (const float*)d_in[4];
    const float* W2    = (const float*)d_in[5];
    const float* g2    = (const float*)d_in[6];
    const float* b2    = (const float*)d_in[7];
    const float* W3    = (const float*)d_in[8];
    const float* g3    = (const float*)d_in[9];
    const float* b3    = (const float*)d_in[10];
    const float* Wfc   = (const float*)d_in[11];
    const float* bfc   = (const float*)d_in[12];
    float* out = (float*)d_out;

    float *bn1, *bn2, *bn3;
    cudaGetSymbolAddress((void**)&bn1, g_bn1);
    cudaGetSymbolAddress((void**)&bn2, g_bn2);
    cudaGetSymbolAddress((void**)&bn3, g_bn3);

    k_scatter<<<NBLK, 256>>>(idx);                    // 1
    k_build<<<NBLK, 256>>>(idx, feats, W1);           // 2
    k_scan<<<1, 320>>>();                             // 3
    k_rank<<<NBLK, 256>>>();                          // 4
    k_finalize<8><<<FBLKS, 256>>>(g1, b1, bn1, 0);    // 5
    k_conv2<<<NBLK, 256>>>(W2);                       // 6  <- ncu -s 5 -c 1
    k_finalize<16><<<FBLKS, 256>>>(g2, b2, bn2, 1);   // 7
    k_conv3<<<NBLK, 256>>>(W3);                       // 8
    k_finalize<32><<<FBLKS, 256>>>(g3, b3, bn3, 2);   // 9
    dim3 pg((NPB + 255) / 256, NB);
    k_pool<<<pg, 256>>>(idx);                         // 10
    k_fc<<<NB, 128>>>(Wfc, bfc, out);                 // 11
    k_unscatter<<<NBLK, 256>>>(idx);                  // 12
}